// round 8
// baseline (speedup 1.0000x reference)
#include <cuda_runtime.h>
#include <cuda_bf16.h>
#include <math.h>
#include <cstdint>

// Fixed problem shapes
#define B_   4
#define T_   2048
#define C_   768
#define H_   12
#define D_   64
#define M_   (B_ * T_)    // 8192
#define N1_  (3 * C_)     // 2304
#define BHD  (B_ * H_)    // 48

// ---------------- scratch (device globals; referenced ONLY in device code) --------
__device__ float g_cosT[T_ * (D_ / 2)];
__device__ float g_sinT[T_ * (D_ / 2)];

// bf16 hi/lo operand buffers
__device__ __nv_bfloat16 g_xh[M_ * C_],  g_xl[M_ * C_];      // x split
__device__ __nv_bfloat16 g_yh[M_ * C_],  g_yl[M_ * C_];      // attn out split
__device__ __nv_bfloat16 g_wah[N1_ * C_], g_wal[N1_ * C_];   // W_attn^T [N][K]
__device__ __nv_bfloat16 g_wph[C_ * C_],  g_wpl[C_ * C_];    // W_proj^T [N][K]
__device__ __nv_bfloat16 g_qh[BHD * T_ * D_], g_ql[BHD * T_ * D_];  // roped q (scaled)
__device__ __nv_bfloat16 g_kh[BHD * T_ * D_], g_kl[BHD * T_ * D_];  // roped k
__device__ __nv_bfloat16 g_vth[BHD * D_ * T_], g_vtl[BHD * D_ * T_]; // V^T [B,H,D,T]

// ---------------- helpers -----------------------------------------------------------
__device__ __forceinline__ uint32_t smem_u32(const void* p) {
    uint32_t a;
    asm("{ .reg .u64 t; cvta.to.shared.u64 t, %1; cvt.u32.u64 %0, t; }" : "=r"(a) : "l"(p));
    return a;
}
#define LDSM_X4(r, a)                                                           \
    asm volatile("ldmatrix.sync.aligned.m8n8.x4.shared.b16 {%0,%1,%2,%3},[%4];" \
        : "=r"((r)[0]), "=r"((r)[1]), "=r"((r)[2]), "=r"((r)[3]) : "r"(a))
#define MMA16816(d, a, b0, b1)                                                  \
    asm volatile("mma.sync.aligned.m16n8k16.row.col.f32.bf16.bf16.f32 "         \
        "{%0,%1,%2,%3},{%4,%5,%6,%7},{%8,%9},{%0,%1,%2,%3};"                    \
        : "+f"((d)[0]), "+f"((d)[1]), "+f"((d)[2]), "+f"((d)[3])                \
        : "r"((a)[0]), "r"((a)[1]), "r"((a)[2]), "r"((a)[3]), "r"(b0), "r"(b1))
#define CP16(dst, src) \
    asm volatile("cp.async.cg.shared.global [%0], [%1], 16;" :: "r"(dst), "l"(src))

__device__ __forceinline__ uint32_t bf2(float a, float b) {
    __nv_bfloat162 t = __floats2bfloat162_rn(a, b);
    return *(uint32_t*)&t;
}
__device__ __forceinline__ float bflo(float v) {   // residual after bf16 round
    return v - __bfloat162float(__float2bfloat16(v));
}

// ---------------- RoPE tables ------------------------------------------------------
__global__ void rope_tables_kernel() {
    int idx = blockIdx.x * blockDim.x + threadIdx.x;
    if (idx >= T_ * 32) return;
    int t = idx >> 5;
    int i = idx & 31;
    double inv = exp(-((double)i / 32.0) * log(10000.0));
    double ang = (double)t * inv;
    g_cosT[idx] = (float)cos(ang);
    g_sinT[idx] = (float)sin(ang);
}

// ---------------- fp32 -> bf16 hi/lo split of x -------------------------------------
__global__ void convert_split_kernel(const float* __restrict__ src) {
    const int n4 = M_ * C_ / 4;
    int i = blockIdx.x * blockDim.x + threadIdx.x;
    if (i >= n4) return;
    float4 v = ((const float4*)src)[i];
    float vv[4] = {v.x, v.y, v.z, v.w};
    uint32_t ph[2], pl[2];
#pragma unroll
    for (int p = 0; p < 2; p++) {
        ph[p] = bf2(vv[p * 2], vv[p * 2 + 1]);
        pl[p] = bf2(bflo(vv[p * 2]), bflo(vv[p * 2 + 1]));
    }
    ((uint2*)g_xh)[i] = make_uint2(ph[0], ph[1]);
    ((uint2*)g_xl)[i] = make_uint2(pl[0], pl[1]);
}

// ---------------- W[K][N] -> W^T[N][K] with hi/lo split -----------------------------
template <int WHICH>
__global__ void convert_wT_kernel(const float* __restrict__ W) {
    const int K = C_;
    const int N = (WHICH == 0) ? N1_ : C_;
    __nv_bfloat16* Th = (WHICH == 0) ? g_wah : g_wph;
    __nv_bfloat16* Tl = (WHICH == 0) ? g_wal : g_wpl;
    __shared__ float tile[32][33];
    int k0 = blockIdx.y * 32, n0 = blockIdx.x * 32;
    int tx = threadIdx.x, ty = threadIdx.y;
    for (int r = ty; r < 32; r += 8)
        tile[r][tx] = W[(size_t)(k0 + r) * N + n0 + tx];
    __syncthreads();
    for (int r = ty; r < 32; r += 8) {
        float v = tile[tx][r];
        size_t o = (size_t)(n0 + r) * K + k0 + tx;
        Th[o] = __float2bfloat16(v);
        Tl[o] = __float2bfloat16(bflo(v));
    }
}

// ---------------- mma.sync GEMM (same as round 7) -----------------------------------
#define STAGE_B   40960
#define TILE_B    10240
#define GEMM_SMEM (2 * STAGE_B)

template <int NT, int EPI>
__global__ __launch_bounds__(256, 2) void tc_gemm_kernel(
    const float* __restrict__ bias, float* __restrict__ Cout)
{
    extern __shared__ __align__(128) char smem[];
    const uint32_t sb0 = smem_u32(smem);
    const int tid  = threadIdx.x;
    const int lane = tid & 31;
    const int warp = tid >> 5;
    const int m_w  = (warp >> 1) * 32;
    const int n_w  = (warp & 1) * 64;
    const int m0 = blockIdx.y * 128;
    const int n0 = blockIdx.x * 128;

    const __nv_bfloat16* srcs[4];
    if (EPI == 1) { srcs[0] = g_xh; srcs[1] = g_xl; srcs[2] = g_wah; srcs[3] = g_wal; }
    else          { srcs[0] = g_yh; srcs[1] = g_yl; srcs[2] = g_wph; srcs[3] = g_wpl; }

    auto load_chunk = [&](int kc, int st) {
        const uint32_t sbase = sb0 + (uint32_t)st * STAGE_B;
        const int k0 = kc * 32;
#pragma unroll
        for (int it = 0; it < 8; ++it) {
            int idx  = it * 256 + tid;
            int tile = idx >> 9;
            int r    = (idx >> 2) & 127;
            int seg  = idx & 3;
            int rowbase = ((tile < 2) ? m0 : n0) + r;
            const void* g = srcs[tile] + (size_t)rowbase * C_ + k0 + seg * 8;
            uint32_t dst = sbase + (uint32_t)tile * TILE_B + (uint32_t)(r * 80 + seg * 16);
            CP16(dst, g);
        }
        asm volatile("cp.async.commit_group;" ::: "memory");
    };

    float acc[2][8][4];
#pragma unroll
    for (int i = 0; i < 2; i++)
#pragma unroll
        for (int j = 0; j < 8; j++)
#pragma unroll
            for (int r = 0; r < 4; r++) acc[i][j][r] = 0.f;

    load_chunk(0, 0);
    const int NCHUNK = C_ / 32;
    for (int c = 0; c < NCHUNK; ++c) {
        const int st = c & 1;
        if (c + 1 < NCHUNK) {
            load_chunk(c + 1, st ^ 1);
            asm volatile("cp.async.wait_group 1;" ::: "memory");
        } else {
            asm volatile("cp.async.wait_group 0;" ::: "memory");
        }
        __syncthreads();

        const uint32_t sA_h = sb0 + (uint32_t)st * STAGE_B;
        const uint32_t sA_l = sA_h + TILE_B;
        const uint32_t sB_h = sA_h + 2 * TILE_B;
        const uint32_t sB_l = sA_h + 3 * TILE_B;

        uint32_t aH[2][2][4], aL[2][2][4];
#pragma unroll
        for (int ks = 0; ks < 2; ks++)
#pragma unroll
            for (int i = 0; i < 2; i++) {
                uint32_t ra = (uint32_t)((m_w + i * 16 + (lane & 15)) * 80 +
                                         ks * 32 + ((lane >> 4) & 1) * 16);
                LDSM_X4(aH[ks][i], sA_h + ra);
                LDSM_X4(aL[ks][i], sA_l + ra);
            }
#pragma unroll
        for (int j = 0; j < 8; j++) {
            uint32_t rb = (uint32_t)((n_w + j * 8 + (lane & 7)) * 80 +
                                     ((lane >> 3) & 3) * 16);
            uint32_t bH[4], bL[4];
            LDSM_X4(bH, sB_h + rb);
            LDSM_X4(bL, sB_l + rb);
#pragma unroll
            for (int ks = 0; ks < 2; ks++)
#pragma unroll
                for (int i = 0; i < 2; i++) {
                    MMA16816(acc[i][j], aH[ks][i], bH[ks * 2], bH[ks * 2 + 1]);
                    MMA16816(acc[i][j], aH[ks][i], bL[ks * 2], bL[ks * 2 + 1]);
                    MMA16816(acc[i][j], aL[ks][i], bH[ks * 2], bH[ks * 2 + 1]);
                }
        }
        __syncthreads();
    }

    // ---- stage results (bias added) into smem ----
    float* stg = (float*)smem;   // 128 x 132
#pragma unroll
    for (int i = 0; i < 2; i++) {
        int row = m_w + i * 16 + (lane >> 2);
#pragma unroll
        for (int j = 0; j < 8; j++) {
            int col = n_w + j * 8 + (lane & 3) * 2;
            float b0 = bias[n0 + col], b1 = bias[n0 + col + 1];
            stg[row * 132 + col]           = acc[i][j][0] + b0;
            stg[row * 132 + col + 1]       = acc[i][j][1] + b1;
            stg[(row + 8) * 132 + col]     = acc[i][j][2] + b0;
            stg[(row + 8) * 132 + col + 1] = acc[i][j][3] + b1;
        }
    }
    __syncthreads();

    if (EPI == 0) {
#pragma unroll
        for (int it = 0; it < 16; ++it) {
            int idx = it * 256 + tid;
            int ml = idx >> 5;
            int c4 = (idx & 31) * 4;
            float4 v = *(const float4*)(stg + ml * 132 + c4);
            *(float4*)(Cout + (size_t)(m0 + ml) * NT + n0 + c4) = v;
        }
    } else {
        const int which = n0 / C_;
        const int hbase = (n0 % C_) / 64;
        const int bb = m0 >> 11;
        const int t0 = m0 & (T_ - 1);
        if (which < 2) {
            __nv_bfloat16* dh = which ? g_kh : g_qh;
            __nv_bfloat16* dl = which ? g_kl : g_ql;
            const float sc = which ? 1.0f : 0.125f;
#pragma unroll
            for (int it = 0; it < 16; ++it) {
                int idx = it * 256 + tid;
                int ml = idx >> 5;
                int hl = (idx >> 4) & 1;
                int d  = (idx & 15) * 2;
                int t  = t0 + ml;
                float c0 = g_cosT[(t << 5) + d],     s0 = g_sinT[(t << 5) + d];
                float c1 = g_cosT[(t << 5) + d + 1], s1 = g_sinT[(t << 5) + d + 1];
                const float* row = stg + ml * 132 + hl * 64 + d;
                float x1a = row[0],  x1b = row[1];
                float x2a = row[32], x2b = row[33];
                float y1a = (x1a * c0 + x2a * s0) * sc;
                float y1b = (x1b * c1 + x2b * s1) * sc;
                float y2a = (-x1a * s0 + x2a * c0) * sc;
                float y2b = (-x1b * s1 + x2b * c1) * sc;
                size_t o = ((size_t)(bb * H_ + hbase + hl) * T_ + t) * 64 + d;
                *(uint32_t*)(dh + o)      = bf2(y1a, y1b);
                *(uint32_t*)(dl + o)      = bf2(bflo(y1a), bflo(y1b));
                *(uint32_t*)(dh + o + 32) = bf2(y2a, y2b);
                *(uint32_t*)(dl + o + 32) = bf2(bflo(y2a), bflo(y2b));
            }
        } else {
#pragma unroll
            for (int it = 0; it < 32; ++it) {
                int idx  = it * 256 + tid;
                int dcol = idx >> 6;
                int tp   = (idx & 63) * 2;
                int hl = dcol >> 6;
                int dd = dcol & 63;
                float v0 = stg[tp * 132 + dcol];
                float v1 = stg[(tp + 1) * 132 + dcol];
                size_t o = ((size_t)(bb * H_ + hbase + hl) * 64 + dd) * T_ + t0 + tp;
                *(uint32_t*)(g_vth + o) = bf2(v0, v1);
                *(uint32_t*)(g_vtl + o) = bf2(bflo(v0), bflo(v1));
            }
        }
    }
}

// ---------------- Tensor-core flash attention: 64-k stages, 2 CTA/SM ---------------
// CTA = 128 q rows; 8 warps x 16q. Pipeline stage = 64 k: K hi/lo (64x144B) +
// V^T hi/lo (64 d-rows x 144B). Double-buffered = 72KB -> 2 CTAs/SM.
#define KTILE 64
#define KSTG  (64 * 144)                 // 9216
#define VSTG  (64 * 144)                 // 9216
#define STG_BYTES (2 * KSTG + 2 * VSTG)  // 36864
#define ATTN_SMEM (2 * STG_BYTES)        // 73728

__global__ __launch_bounds__(256, 2) void attn_mma_kernel() {
    extern __shared__ __align__(128) char sm[];
    const uint32_t sb = smem_u32(sm);
    const int tid  = threadIdx.x;
    const int lane = tid & 31;
    const int w    = tid >> 5;
    const int bh   = blockIdx.y;
    const int qb   = (int)gridDim.x - 1 - (int)blockIdx.x;   // longest first
    const int b    = bh / H_;
    const int h    = bh - b * H_;
    const size_t hb = (size_t)bh * T_ * D_;
    const int qbase = qb * 128;
    const int r0 = lane >> 2;
    const int c2 = (lane & 3) * 2;
    const int row_a = qbase + w * 16 + r0;

    // Q A-fragments (direct 4B global loads; pairs are d-contiguous)
    uint32_t qfh[4][4], qfl[4][4];
#pragma unroll
    for (int ks = 0; ks < 4; ks++) {
        int d = ks * 16 + c2;
        size_t o0 = hb + (size_t)row_a * 64 + d;
        size_t o1 = hb + (size_t)(row_a + 8) * 64 + d;
        qfh[ks][0] = *(const uint32_t*)(g_qh + o0);
        qfh[ks][1] = *(const uint32_t*)(g_qh + o1);
        qfh[ks][2] = *(const uint32_t*)(g_qh + o0 + 8);
        qfh[ks][3] = *(const uint32_t*)(g_qh + o1 + 8);
        qfl[ks][0] = *(const uint32_t*)(g_ql + o0);
        qfl[ks][1] = *(const uint32_t*)(g_ql + o1);
        qfl[ks][2] = *(const uint32_t*)(g_ql + o0 + 8);
        qfl[ks][3] = *(const uint32_t*)(g_ql + o1 + 8);
    }

    const __nv_bfloat16* kh = g_kh + hb;
    const __nv_bfloat16* kl = g_kl + hb;
    const __nv_bfloat16* vh = g_vth + hb;
    const __nv_bfloat16* vl = g_vtl + hb;

    auto load_stage = [&](int kt, int st) {
        const uint32_t sbase = sb + (uint32_t)st * STG_BYTES;
        const int kbase = kt * KTILE;
#pragma unroll
        for (int it = 0; it < 4; ++it) {            // K: 2 tiles x 64 rows x 8 segs
            int idx = it * 256 + tid;
            int tile = idx >> 9;
            int r    = (idx >> 3) & 63;
            int seg  = idx & 7;
            const void* g = (tile ? kl : kh) + (size_t)(kbase + r) * 64 + seg * 8;
            CP16(sbase + (uint32_t)(tile * KSTG + r * 144 + seg * 16), g);
        }
#pragma unroll
        for (int it = 0; it < 4; ++it) {            // V^T: 2 tiles x 64 d-rows x 8 segs
            int idx = it * 256 + tid;
            int tile = idx >> 9;
            int r    = (idx >> 3) & 63;
            int seg  = idx & 7;
            const void* g = (tile ? vl : vh) + (size_t)r * T_ + kbase + seg * 8;
            CP16(sbase + (uint32_t)(2 * KSTG + tile * VSTG + r * 144 + seg * 16), g);
        }
        asm volatile("cp.async.commit_group;" ::: "memory");
    };

    float oacc[8][4];
#pragma unroll
    for (int jd = 0; jd < 8; jd++)
#pragma unroll
        for (int e = 0; e < 4; e++) oacc[jd][e] = 0.f;
    float m0 = -1e30f, m1 = -1e30f, l0 = 0.f, l1 = 0.f;

    const int KT_LAST = 2 * qb + 1;     // tiles cover k in [0, qbase+128)
    load_stage(0, 0);

    for (int kt = 0; kt <= KT_LAST; kt++) {
        const int st = kt & 1;
        if (kt < KT_LAST) {
            load_stage(kt + 1, st ^ 1);
            asm volatile("cp.async.wait_group 1;" ::: "memory");
        } else {
            asm volatile("cp.async.wait_group 0;" ::: "memory");
        }
        __syncthreads();

        const uint32_t kb = sb + (uint32_t)st * STG_BYTES;

        // ---- S = Q K^T (3-pass hi/lo), 8 n8 acc tiles ----
        float sacc[8][4];
#pragma unroll
        for (int j = 0; j < 8; j++)
#pragma unroll
            for (int e = 0; e < 4; e++) sacc[j][e] = 0.f;

#pragma unroll
        for (int j = 0; j < 8; j++) {
            uint32_t rbase = kb + (uint32_t)((j * 8 + (lane & 7)) * 144 +
                                             ((lane >> 3) & 3) * 16);
#pragma unroll
            for (int half = 0; half < 2; half++) {
                uint32_t bH[4], bL[4];
                LDSM_X4(bH, rbase + half * 64);
                LDSM_X4(bL, rbase + KSTG + half * 64);
#pragma unroll
                for (int ki = 0; ki < 2; ki++) {
                    int ks = half * 2 + ki;
                    MMA16816(sacc[j], qfh[ks], bH[ki * 2], bH[ki * 2 + 1]);
                    MMA16816(sacc[j], qfh[ks], bL[ki * 2], bL[ki * 2 + 1]);
                    MMA16816(sacc[j], qfl[ks], bH[ki * 2], bH[ki * 2 + 1]);
                }
            }
        }

        // ---- causal mask on the last two tiles ----
        if (kt >= 2 * qb) {
            const int kbase = kt * KTILE;
#pragma unroll
            for (int j = 0; j < 8; j++) {
                int col = kbase + j * 8 + c2;
                if (col > row_a)         sacc[j][0] = -1e30f;
                if (col + 1 > row_a)     sacc[j][1] = -1e30f;
                if (col > row_a + 8)     sacc[j][2] = -1e30f;
                if (col + 1 > row_a + 8) sacc[j][3] = -1e30f;
            }
        }

        // ---- online softmax ----
        float mx0 = -1e30f, mx1 = -1e30f;
#pragma unroll
        for (int j = 0; j < 8; j++) {
            mx0 = fmaxf(mx0, fmaxf(sacc[j][0], sacc[j][1]));
            mx1 = fmaxf(mx1, fmaxf(sacc[j][2], sacc[j][3]));
        }
        mx0 = fmaxf(mx0, __shfl_xor_sync(0xffffffffu, mx0, 1));
        mx0 = fmaxf(mx0, __shfl_xor_sync(0xffffffffu, mx0, 2));
        mx1 = fmaxf(mx1, __shfl_xor_sync(0xffffffffu, mx1, 1));
        mx1 = fmaxf(mx1, __shfl_xor_sync(0xffffffffu, mx1, 2));
        float mn0 = fmaxf(m0, mx0), mn1 = fmaxf(m1, mx1);
        float a0 = __expf(m0 - mn0), a1 = __expf(m1 - mn1);
        m0 = mn0; m1 = mn1;
        float s0 = 0.f, s1 = 0.f;
#pragma unroll
        for (int j = 0; j < 8; j++) {
            sacc[j][0] = __expf(sacc[j][0] - m0);
            sacc[j][1] = __expf(sacc[j][1] - m0);
            sacc[j][2] = __expf(sacc[j][2] - m1);
            sacc[j][3] = __expf(sacc[j][3] - m1);
            s0 += sacc[j][0] + sacc[j][1];
            s1 += sacc[j][2] + sacc[j][3];
        }
        l0 = l0 * a0 + s0;
        l1 = l1 * a1 + s1;
#pragma unroll
        for (int jd = 0; jd < 8; jd++) {
            oacc[jd][0] *= a0; oacc[jd][1] *= a0;
            oacc[jd][2] *= a1; oacc[jd][3] *= a1;
        }

        // ---- PV: O += P V (P hi/lo from acc frags, V^T hi/lo, 3-pass) ----
        const uint32_t vb = kb + 2 * KSTG;
#pragma unroll
        for (int koff = 0; koff < 2; koff++) {
            uint32_t pah[2][4], pal[2][4];
#pragma unroll
            for (int ki = 0; ki < 2; ki++) {
                int j0 = koff * 4 + ki * 2;
                pah[ki][0] = bf2(sacc[j0][0],     sacc[j0][1]);
                pah[ki][1] = bf2(sacc[j0][2],     sacc[j0][3]);
                pah[ki][2] = bf2(sacc[j0 + 1][0], sacc[j0 + 1][1]);
                pah[ki][3] = bf2(sacc[j0 + 1][2], sacc[j0 + 1][3]);
                pal[ki][0] = bf2(bflo(sacc[j0][0]),     bflo(sacc[j0][1]));
                pal[ki][1] = bf2(bflo(sacc[j0][2]),     bflo(sacc[j0][3]));
                pal[ki][2] = bf2(bflo(sacc[j0 + 1][0]), bflo(sacc[j0 + 1][1]));
                pal[ki][3] = bf2(bflo(sacc[j0 + 1][2]), bflo(sacc[j0 + 1][3]));
            }
#pragma unroll
            for (int jd = 0; jd < 8; jd++) {
                uint32_t rv = vb + (uint32_t)((jd * 8 + (lane & 7)) * 144 +
                                              ((lane >> 3) & 3) * 16 + koff * 64);
                uint32_t vH[4], vL[4];
                LDSM_X4(vH, rv);
                LDSM_X4(vL, rv + VSTG);
#pragma unroll
                for (int ki = 0; ki < 2; ki++) {
                    MMA16816(oacc[jd], pah[ki], vH[ki * 2], vH[ki * 2 + 1]);
                    MMA16816(oacc[jd], pah[ki], vL[ki * 2], vL[ki * 2 + 1]);
                    MMA16816(oacc[jd], pal[ki], vH[ki * 2], vH[ki * 2 + 1]);
                }
            }
        }
        __syncthreads();
    }

    // ---- epilogue: normalize, split hi/lo, store ----
    l0 += __shfl_xor_sync(0xffffffffu, l0, 1);
    l0 += __shfl_xor_sync(0xffffffffu, l0, 2);
    l1 += __shfl_xor_sync(0xffffffffu, l1, 1);
    l1 += __shfl_xor_sync(0xffffffffu, l1, 2);
    const float inv0 = 1.f / l0, inv1 = 1.f / l1;
    const size_t y0 = ((size_t)(b * T_) + row_a) * C_ + h * 64;
    const size_t y1 = ((size_t)(b * T_) + row_a + 8) * C_ + h * 64;
#pragma unroll
    for (int jd = 0; jd < 8; jd++) {
        int d = jd * 8 + c2;
        float v00 = oacc[jd][0] * inv0, v01 = oacc[jd][1] * inv0;
        float v10 = oacc[jd][2] * inv1, v11 = oacc[jd][3] * inv1;
        *(uint32_t*)(g_yh + y0 + d) = bf2(v00, v01);
        *(uint32_t*)(g_yl + y0 + d) = bf2(bflo(v00), bflo(v01));
        *(uint32_t*)(g_yh + y1 + d) = bf2(v10, v11);
        *(uint32_t*)(g_yl + y1 + d) = bf2(bflo(v10), bflo(v11));
    }
}

// ---------------- launch ------------------------------------------------------------
extern "C" void kernel_launch(void* const* d_in, const int* in_sizes, int n_in,
                              void* d_out, int out_size) {
    (void)in_sizes; (void)n_in; (void)out_size;
    const float* x      = (const float*)d_in[0];
    const float* W_attn = (const float*)d_in[1];
    const float* b_attn = (const float*)d_in[2];
    const float* W_proj = (const float*)d_in[3];
    const float* b_proj = (const float*)d_in[4];
    float* out = (float*)d_out;

    cudaFuncSetAttribute(attn_mma_kernel, cudaFuncAttributeMaxDynamicSharedMemorySize,
                         ATTN_SMEM);
    cudaFuncSetAttribute(tc_gemm_kernel<N1_, 1>,
                         cudaFuncAttributeMaxDynamicSharedMemorySize, GEMM_SMEM);
    cudaFuncSetAttribute(tc_gemm_kernel<C_, 0>,
                         cudaFuncAttributeMaxDynamicSharedMemorySize, GEMM_SMEM);

    rope_tables_kernel<<<(T_ * 32 + 255) / 256, 256>>>();
    convert_split_kernel<<<(M_ * C_ / 4 + 255) / 256, 256>>>(x);
    convert_wT_kernel<0><<<dim3(N1_ / 32, C_ / 32), dim3(32, 8)>>>(W_attn);
    convert_wT_kernel<1><<<dim3(C_ / 32, C_ / 32), dim3(32, 8)>>>(W_proj);

    tc_gemm_kernel<N1_, 1><<<dim3(N1_ / 128, M_ / 128), 256, GEMM_SMEM>>>(b_attn, nullptr);

    attn_mma_kernel<<<dim3(T_ / 128, BHD), 256, ATTN_SMEM>>>();

    tc_gemm_kernel<C_, 0><<<dim3(C_ / 128, M_ / 128), 256, GEMM_SMEM>>>(b_proj, out);
}

// round 9
// speedup vs baseline: 1.3272x; 1.3272x over previous
#include <cuda_runtime.h>
#include <cuda_bf16.h>
#include <cuda_fp16.h>
#include <math.h>
#include <cstdint>

// Fixed problem shapes
#define B_   4
#define T_   2048
#define C_   768
#define H_   12
#define D_   64
#define M_   (B_ * T_)    // 8192
#define N1_  (3 * C_)     // 2304
#define BHD  (B_ * H_)    // 48

// ---------------- scratch (device globals; referenced ONLY in device code) --------
__device__ float g_cosT[T_ * (D_ / 2)];
__device__ float g_sinT[T_ * (D_ / 2)];

// bf16 hi/lo operand buffers (GEMMs)
__device__ __nv_bfloat16 g_xh[M_ * C_],  g_xl[M_ * C_];      // x split
__device__ __nv_bfloat16 g_yh[M_ * C_],  g_yl[M_ * C_];      // attn out split
__device__ __nv_bfloat16 g_wah[N1_ * C_], g_wal[N1_ * C_];   // W_attn^T [N][K]
__device__ __nv_bfloat16 g_wph[C_ * C_],  g_wpl[C_ * C_];    // W_proj^T [N][K]
// fp16 attention operands (single precision pass)
__device__ __half g_qh[BHD * T_ * D_];   // roped q (scaled 1/8), [B,H,T,D]
__device__ __half g_kh[BHD * T_ * D_];   // roped k
__device__ __half g_vth[BHD * D_ * T_];  // V^T [B,H,D,T]

// ---------------- helpers -----------------------------------------------------------
__device__ __forceinline__ uint32_t smem_u32(const void* p) {
    uint32_t a;
    asm("{ .reg .u64 t; cvta.to.shared.u64 t, %1; cvt.u32.u64 %0, t; }" : "=r"(a) : "l"(p));
    return a;
}
#define LDSM_X4(r, a)                                                           \
    asm volatile("ldmatrix.sync.aligned.m8n8.x4.shared.b16 {%0,%1,%2,%3},[%4];" \
        : "=r"((r)[0]), "=r"((r)[1]), "=r"((r)[2]), "=r"((r)[3]) : "r"(a))
#define MMA16816(d, a, b0, b1)                                                  \
    asm volatile("mma.sync.aligned.m16n8k16.row.col.f32.bf16.bf16.f32 "         \
        "{%0,%1,%2,%3},{%4,%5,%6,%7},{%8,%9},{%0,%1,%2,%3};"                    \
        : "+f"((d)[0]), "+f"((d)[1]), "+f"((d)[2]), "+f"((d)[3])                \
        : "r"((a)[0]), "r"((a)[1]), "r"((a)[2]), "r"((a)[3]), "r"(b0), "r"(b1))
#define MMAF16(d, a, b0, b1)                                                    \
    asm volatile("mma.sync.aligned.m16n8k16.row.col.f32.f16.f16.f32 "           \
        "{%0,%1,%2,%3},{%4,%5,%6,%7},{%8,%9},{%0,%1,%2,%3};"                    \
        : "+f"((d)[0]), "+f"((d)[1]), "+f"((d)[2]), "+f"((d)[3])                \
        : "r"((a)[0]), "r"((a)[1]), "r"((a)[2]), "r"((a)[3]), "r"(b0), "r"(b1))
#define CP16(dst, src) \
    asm volatile("cp.async.cg.shared.global [%0], [%1], 16;" :: "r"(dst), "l"(src))

__device__ __forceinline__ uint32_t bf2(float a, float b) {
    __nv_bfloat162 t = __floats2bfloat162_rn(a, b);
    return *(uint32_t*)&t;
}
__device__ __forceinline__ uint32_t h2(float a, float b) {
    __half2 t = __floats2half2_rn(a, b);
    return *(uint32_t*)&t;
}
__device__ __forceinline__ float bflo(float v) {   // residual after bf16 round
    return v - __bfloat162float(__float2bfloat16(v));
}

// ---------------- RoPE tables ------------------------------------------------------
__global__ void rope_tables_kernel() {
    int idx = blockIdx.x * blockDim.x + threadIdx.x;
    if (idx >= T_ * 32) return;
    int t = idx >> 5;
    int i = idx & 31;
    double inv = exp(-((double)i / 32.0) * log(10000.0));
    double ang = (double)t * inv;
    g_cosT[idx] = (float)cos(ang);
    g_sinT[idx] = (float)sin(ang);
}

// ---------------- fp32 -> bf16 hi/lo split of x -------------------------------------
__global__ void convert_split_kernel(const float* __restrict__ src) {
    const int n4 = M_ * C_ / 4;
    int i = blockIdx.x * blockDim.x + threadIdx.x;
    if (i >= n4) return;
    float4 v = ((const float4*)src)[i];
    float vv[4] = {v.x, v.y, v.z, v.w};
    uint32_t ph[2], pl[2];
#pragma unroll
    for (int p = 0; p < 2; p++) {
        ph[p] = bf2(vv[p * 2], vv[p * 2 + 1]);
        pl[p] = bf2(bflo(vv[p * 2]), bflo(vv[p * 2 + 1]));
    }
    ((uint2*)g_xh)[i] = make_uint2(ph[0], ph[1]);
    ((uint2*)g_xl)[i] = make_uint2(pl[0], pl[1]);
}

// ---------------- W[K][N] -> W^T[N][K] with hi/lo split -----------------------------
template <int WHICH>
__global__ void convert_wT_kernel(const float* __restrict__ W) {
    const int K = C_;
    const int N = (WHICH == 0) ? N1_ : C_;
    __nv_bfloat16* Th = (WHICH == 0) ? g_wah : g_wph;
    __nv_bfloat16* Tl = (WHICH == 0) ? g_wal : g_wpl;
    __shared__ float tile[32][33];
    int k0 = blockIdx.y * 32, n0 = blockIdx.x * 32;
    int tx = threadIdx.x, ty = threadIdx.y;
    for (int r = ty; r < 32; r += 8)
        tile[r][tx] = W[(size_t)(k0 + r) * N + n0 + tx];
    __syncthreads();
    for (int r = ty; r < 32; r += 8) {
        float v = tile[tx][r];
        size_t o = (size_t)(n0 + r) * K + k0 + tx;
        Th[o] = __float2bfloat16(v);
        Tl[o] = __float2bfloat16(bflo(v));
    }
}

// ---------------- mma.sync GEMM: bf16 hi/lo 3-pass ----------------------------------
// EPI==1 (QKV): fused epilogue — RoPE q/k (q scaled 1/8) -> fp16 g_qh/g_kh,
//               V transposed -> fp16 g_vth.
// EPI==0 (proj): A = g_yh/g_yl, B = g_wph/g_wpl, fp32 out + bias.
#define STAGE_B   40960
#define TILE_B    10240
#define GEMM_SMEM (2 * STAGE_B)

template <int NT, int EPI>
__global__ __launch_bounds__(256, 2) void tc_gemm_kernel(
    const float* __restrict__ bias, float* __restrict__ Cout)
{
    extern __shared__ __align__(128) char smem[];
    const uint32_t sb0 = smem_u32(smem);
    const int tid  = threadIdx.x;
    const int lane = tid & 31;
    const int warp = tid >> 5;
    const int m_w  = (warp >> 1) * 32;
    const int n_w  = (warp & 1) * 64;
    const int m0 = blockIdx.y * 128;
    const int n0 = blockIdx.x * 128;

    const __nv_bfloat16* srcs[4];
    if (EPI == 1) { srcs[0] = g_xh; srcs[1] = g_xl; srcs[2] = g_wah; srcs[3] = g_wal; }
    else          { srcs[0] = g_yh; srcs[1] = g_yl; srcs[2] = g_wph; srcs[3] = g_wpl; }

    auto load_chunk = [&](int kc, int st) {
        const uint32_t sbase = sb0 + (uint32_t)st * STAGE_B;
        const int k0 = kc * 32;
#pragma unroll
        for (int it = 0; it < 8; ++it) {
            int idx  = it * 256 + tid;
            int tile = idx >> 9;
            int r    = (idx >> 2) & 127;
            int seg  = idx & 3;
            int rowbase = ((tile < 2) ? m0 : n0) + r;
            const void* g = srcs[tile] + (size_t)rowbase * C_ + k0 + seg * 8;
            uint32_t dst = sbase + (uint32_t)tile * TILE_B + (uint32_t)(r * 80 + seg * 16);
            CP16(dst, g);
        }
        asm volatile("cp.async.commit_group;" ::: "memory");
    };

    float acc[2][8][4];
#pragma unroll
    for (int i = 0; i < 2; i++)
#pragma unroll
        for (int j = 0; j < 8; j++)
#pragma unroll
            for (int r = 0; r < 4; r++) acc[i][j][r] = 0.f;

    load_chunk(0, 0);
    const int NCHUNK = C_ / 32;
    for (int c = 0; c < NCHUNK; ++c) {
        const int st = c & 1;
        if (c + 1 < NCHUNK) {
            load_chunk(c + 1, st ^ 1);
            asm volatile("cp.async.wait_group 1;" ::: "memory");
        } else {
            asm volatile("cp.async.wait_group 0;" ::: "memory");
        }
        __syncthreads();

        const uint32_t sA_h = sb0 + (uint32_t)st * STAGE_B;
        const uint32_t sA_l = sA_h + TILE_B;
        const uint32_t sB_h = sA_h + 2 * TILE_B;
        const uint32_t sB_l = sA_h + 3 * TILE_B;

        uint32_t aH[2][2][4], aL[2][2][4];
#pragma unroll
        for (int ks = 0; ks < 2; ks++)
#pragma unroll
            for (int i = 0; i < 2; i++) {
                uint32_t ra = (uint32_t)((m_w + i * 16 + (lane & 15)) * 80 +
                                         ks * 32 + ((lane >> 4) & 1) * 16);
                LDSM_X4(aH[ks][i], sA_h + ra);
                LDSM_X4(aL[ks][i], sA_l + ra);
            }
#pragma unroll
        for (int j = 0; j < 8; j++) {
            uint32_t rb = (uint32_t)((n_w + j * 8 + (lane & 7)) * 80 +
                                     ((lane >> 3) & 3) * 16);
            uint32_t bH[4], bL[4];
            LDSM_X4(bH, sB_h + rb);
            LDSM_X4(bL, sB_l + rb);
#pragma unroll
            for (int ks = 0; ks < 2; ks++)
#pragma unroll
                for (int i = 0; i < 2; i++) {
                    MMA16816(acc[i][j], aH[ks][i], bH[ks * 2], bH[ks * 2 + 1]);
                    MMA16816(acc[i][j], aH[ks][i], bL[ks * 2], bL[ks * 2 + 1]);
                    MMA16816(acc[i][j], aL[ks][i], bH[ks * 2], bH[ks * 2 + 1]);
                }
        }
        __syncthreads();
    }

    // ---- stage results (bias added) into smem ----
    float* stg = (float*)smem;   // 128 x 132
#pragma unroll
    for (int i = 0; i < 2; i++) {
        int row = m_w + i * 16 + (lane >> 2);
#pragma unroll
        for (int j = 0; j < 8; j++) {
            int col = n_w + j * 8 + (lane & 3) * 2;
            float b0 = bias[n0 + col], b1 = bias[n0 + col + 1];
            stg[row * 132 + col]           = acc[i][j][0] + b0;
            stg[row * 132 + col + 1]       = acc[i][j][1] + b1;
            stg[(row + 8) * 132 + col]     = acc[i][j][2] + b0;
            stg[(row + 8) * 132 + col + 1] = acc[i][j][3] + b1;
        }
    }
    __syncthreads();

    if (EPI == 0) {
#pragma unroll
        for (int it = 0; it < 16; ++it) {
            int idx = it * 256 + tid;
            int ml = idx >> 5;
            int c4 = (idx & 31) * 4;
            float4 v = *(const float4*)(stg + ml * 132 + c4);
            *(float4*)(Cout + (size_t)(m0 + ml) * NT + n0 + c4) = v;
        }
    } else {
        const int which = n0 / C_;               // 0=q 1=k 2=v
        const int hbase = (n0 % C_) / 64;
        const int bb = m0 >> 11;
        const int t0 = m0 & (T_ - 1);
        if (which < 2) {
            __half* dh = which ? g_kh : g_qh;
            const float sc = which ? 1.0f : 0.125f;
#pragma unroll
            for (int it = 0; it < 16; ++it) {
                int idx = it * 256 + tid;
                int ml = idx >> 5;
                int hl = (idx >> 4) & 1;
                int d  = (idx & 15) * 2;
                int t  = t0 + ml;
                float c0 = g_cosT[(t << 5) + d],     s0 = g_sinT[(t << 5) + d];
                float c1 = g_cosT[(t << 5) + d + 1], s1 = g_sinT[(t << 5) + d + 1];
                const float* row = stg + ml * 132 + hl * 64 + d;
                float x1a = row[0],  x1b = row[1];
                float x2a = row[32], x2b = row[33];
                float y1a = (x1a * c0 + x2a * s0) * sc;
                float y1b = (x1b * c1 + x2b * s1) * sc;
                float y2a = (-x1a * s0 + x2a * c0) * sc;
                float y2b = (-x1b * s1 + x2b * c1) * sc;
                size_t o = ((size_t)(bb * H_ + hbase + hl) * T_ + t) * 64 + d;
                *(uint32_t*)(dh + o)      = h2(y1a, y1b);
                *(uint32_t*)(dh + o + 32) = h2(y2a, y2b);
            }
        } else {
            // V: transpose into g_vth [bh][d][t] (fp16)
#pragma unroll
            for (int it = 0; it < 32; ++it) {
                int idx  = it * 256 + tid;
                int dcol = idx >> 6;
                int tp   = (idx & 63) * 2;
                int hl = dcol >> 6;
                int dd = dcol & 63;
                float v0 = stg[tp * 132 + dcol];
                float v1 = stg[(tp + 1) * 132 + dcol];
                size_t o = ((size_t)(bb * H_ + hbase + hl) * 64 + dd) * T_ + t0 + tp;
                *(uint32_t*)(g_vth + o) = h2(v0, v1);
            }
        }
    }
}

// ---------------- Tensor-core flash attention: fp16 single-pass --------------------
// CTA = 128 q rows; 8 warps x 16q x full 128-k tile. QK^T and PV single-pass fp16
// (fp32 accum). Stage = K (128x144B) + V^T (64x272B) = 35840B, double buffered.
#define KSTG  (128 * 144)                // 18432
#define VSTG  (64 * 272)                 // 17408
#define STG_BYTES (KSTG + VSTG)          // 35840
#define ATTN_SMEM (2 * STG_BYTES)        // 71680

__global__ __launch_bounds__(256, 1) void attn_mma_kernel() {
    extern __shared__ __align__(128) char sm[];
    const uint32_t sb = smem_u32(sm);
    const int tid  = threadIdx.x;
    const int lane = tid & 31;
    const int w    = tid >> 5;
    const int bh   = blockIdx.y;
    const int qb   = (int)gridDim.x - 1 - (int)blockIdx.x;   // longest first
    const int b    = bh / H_;
    const int h    = bh - b * H_;
    const size_t hb = (size_t)bh * T_ * D_;
    const int qbase = qb * 128;
    const int r0 = lane >> 2;
    const int c2 = (lane & 3) * 2;
    const int row_a = qbase + w * 16 + r0;

    // Q A-fragments: fp16, direct 4B global loads (pairs are d-contiguous)
    uint32_t qf[4][4];
#pragma unroll
    for (int ks = 0; ks < 4; ks++) {
        int d = ks * 16 + c2;
        size_t o0 = hb + (size_t)row_a * 64 + d;
        size_t o1 = hb + (size_t)(row_a + 8) * 64 + d;
        qf[ks][0] = *(const uint32_t*)(g_qh + o0);
        qf[ks][1] = *(const uint32_t*)(g_qh + o1);
        qf[ks][2] = *(const uint32_t*)(g_qh + o0 + 8);
        qf[ks][3] = *(const uint32_t*)(g_qh + o1 + 8);
    }

    const __half* kh = g_kh + hb;
    const __half* vh = g_vth + hb;

    auto load_stage = [&](int kt, int st) {
        const uint32_t sbase = sb + (uint32_t)st * STG_BYTES;
        const int kbase = kt * 128;
#pragma unroll
        for (int it = 0; it < 4; ++it) {            // K: 128 rows x 8 segs
            int idx = it * 256 + tid;
            int r   = idx >> 3;
            int seg = idx & 7;
            const void* g = kh + (size_t)(kbase + r) * 64 + seg * 8;
            CP16(sbase + (uint32_t)(r * 144 + seg * 16), g);
        }
#pragma unroll
        for (int it = 0; it < 4; ++it) {            // V^T: 64 d-rows x 16 segs
            int idx = it * 256 + tid;
            int r   = idx >> 4;
            int seg = idx & 15;
            const void* g = vh + (size_t)r * T_ + kbase + seg * 8;
            CP16(sbase + (uint32_t)(KSTG + r * 272 + seg * 16), g);
        }
        asm volatile("cp.async.commit_group;" ::: "memory");
    };

    float oacc[8][4];
#pragma unroll
    for (int jd = 0; jd < 8; jd++)
#pragma unroll
        for (int e = 0; e < 4; e++) oacc[jd][e] = 0.f;
    float m0 = -1e30f, m1 = -1e30f, l0 = 0.f, l1 = 0.f;

    load_stage(0, 0);

    for (int kt = 0; kt <= qb; kt++) {
        const int st = kt & 1;
        if (kt < qb) {
            load_stage(kt + 1, st ^ 1);
            asm volatile("cp.async.wait_group 1;" ::: "memory");
        } else {
            asm volatile("cp.async.wait_group 0;" ::: "memory");
        }
        __syncthreads();

        const uint32_t kb = sb + (uint32_t)st * STG_BYTES;

        // ---- S = Q K^T (single-pass fp16), 16 n8 acc tiles ----
        float sacc[16][4];
#pragma unroll
        for (int j = 0; j < 16; j++)
#pragma unroll
            for (int e = 0; e < 4; e++) sacc[j][e] = 0.f;

#pragma unroll
        for (int j = 0; j < 16; j++) {
            uint32_t rbase = kb + (uint32_t)((j * 8 + (lane & 7)) * 144 +
                                             ((lane >> 3) & 3) * 16);
#pragma unroll
            for (int half = 0; half < 2; half++) {
                uint32_t bF[4];
                LDSM_X4(bF, rbase + half * 64);
#pragma unroll
                for (int ki = 0; ki < 2; ki++) {
                    int ks = half * 2 + ki;
                    MMAF16(sacc[j], qf[ks], bF[ki * 2], bF[ki * 2 + 1]);
                }
            }
        }

        // ---- causal mask on diagonal tile ----
        if (kt == qb) {
            const int kbase = kt * 128;
#pragma unroll
            for (int j = 0; j < 16; j++) {
                int col = kbase + j * 8 + c2;
                if (col > row_a)         sacc[j][0] = -1e30f;
                if (col + 1 > row_a)     sacc[j][1] = -1e30f;
                if (col > row_a + 8)     sacc[j][2] = -1e30f;
                if (col + 1 > row_a + 8) sacc[j][3] = -1e30f;
            }
        }

        // ---- online softmax ----
        float mx0 = -1e30f, mx1 = -1e30f;
#pragma unroll
        for (int j = 0; j < 16; j++) {
            mx0 = fmaxf(mx0, fmaxf(sacc[j][0], sacc[j][1]));
            mx1 = fmaxf(mx1, fmaxf(sacc[j][2], sacc[j][3]));
        }
        mx0 = fmaxf(mx0, __shfl_xor_sync(0xffffffffu, mx0, 1));
        mx0 = fmaxf(mx0, __shfl_xor_sync(0xffffffffu, mx0, 2));
        mx1 = fmaxf(mx1, __shfl_xor_sync(0xffffffffu, mx1, 1));
        mx1 = fmaxf(mx1, __shfl_xor_sync(0xffffffffu, mx1, 2));
        float mn0 = fmaxf(m0, mx0), mn1 = fmaxf(m1, mx1);
        float a0 = __expf(m0 - mn0), a1 = __expf(m1 - mn1);
        m0 = mn0; m1 = mn1;
        float s0 = 0.f, s1 = 0.f;
#pragma unroll
        for (int j = 0; j < 16; j++) {
            sacc[j][0] = __expf(sacc[j][0] - m0);
            sacc[j][1] = __expf(sacc[j][1] - m0);
            sacc[j][2] = __expf(sacc[j][2] - m1);
            sacc[j][3] = __expf(sacc[j][3] - m1);
            s0 += sacc[j][0] + sacc[j][1];
            s1 += sacc[j][2] + sacc[j][3];
        }
        l0 = l0 * a0 + s0;
        l1 = l1 * a1 + s1;
#pragma unroll
        for (int jd = 0; jd < 8; jd++) {
            oacc[jd][0] *= a0; oacc[jd][1] *= a0;
            oacc[jd][2] *= a1; oacc[jd][3] *= a1;
        }

        // ---- PV: O += P V (P fp16 from acc frags, V^T fp16, single pass) ----
        const uint32_t vb = kb + KSTG;
#pragma unroll
        for (int koff = 0; koff < 4; koff++) {
            uint32_t pa[2][4];
#pragma unroll
            for (int ki = 0; ki < 2; ki++) {
                int j0 = (koff * 2 + ki) * 2;
                pa[ki][0] = h2(sacc[j0][0],     sacc[j0][1]);
                pa[ki][1] = h2(sacc[j0][2],     sacc[j0][3]);
                pa[ki][2] = h2(sacc[j0 + 1][0], sacc[j0 + 1][1]);
                pa[ki][3] = h2(sacc[j0 + 1][2], sacc[j0 + 1][3]);
            }
#pragma unroll
            for (int jd = 0; jd < 8; jd++) {
                uint32_t rv = vb + (uint32_t)((jd * 8 + (lane & 7)) * 272 +
                                              ((lane >> 3) & 3) * 16 + koff * 64);
                uint32_t vF[4];
                LDSM_X4(vF, rv);
#pragma unroll
                for (int ki = 0; ki < 2; ki++)
                    MMAF16(oacc[jd], pa[ki], vF[ki * 2], vF[ki * 2 + 1]);
            }
        }
        __syncthreads();
    }

    // ---- epilogue: normalize, bf16 hi/lo split, store (proj GEMM input) ----
    l0 += __shfl_xor_sync(0xffffffffu, l0, 1);
    l0 += __shfl_xor_sync(0xffffffffu, l0, 2);
    l1 += __shfl_xor_sync(0xffffffffu, l1, 1);
    l1 += __shfl_xor_sync(0xffffffffu, l1, 2);
    const float inv0 = 1.f / l0, inv1 = 1.f / l1;
    const size_t y0 = ((size_t)(b * T_) + row_a) * C_ + h * 64;
    const size_t y1 = ((size_t)(b * T_) + row_a + 8) * C_ + h * 64;
#pragma unroll
    for (int jd = 0; jd < 8; jd++) {
        int d = jd * 8 + c2;
        float v00 = oacc[jd][0] * inv0, v01 = oacc[jd][1] * inv0;
        float v10 = oacc[jd][2] * inv1, v11 = oacc[jd][3] * inv1;
        *(uint32_t*)(g_yh + y0 + d) = bf2(v00, v01);
        *(uint32_t*)(g_yl + y0 + d) = bf2(bflo(v00), bflo(v01));
        *(uint32_t*)(g_yh + y1 + d) = bf2(v10, v11);
        *(uint32_t*)(g_yl + y1 + d) = bf2(bflo(v10), bflo(v11));
    }
}

// ---------------- launch ------------------------------------------------------------
extern "C" void kernel_launch(void* const* d_in, const int* in_sizes, int n_in,
                              void* d_out, int out_size) {
    (void)in_sizes; (void)n_in; (void)out_size;
    const float* x      = (const float*)d_in[0];
    const float* W_attn = (const float*)d_in[1];
    const float* b_attn = (const float*)d_in[2];
    const float* W_proj = (const float*)d_in[3];
    const float* b_proj = (const float*)d_in[4];
    float* out = (float*)d_out;

    cudaFuncSetAttribute(attn_mma_kernel, cudaFuncAttributeMaxDynamicSharedMemorySize,
                         ATTN_SMEM);
    cudaFuncSetAttribute(tc_gemm_kernel<N1_, 1>,
                         cudaFuncAttributeMaxDynamicSharedMemorySize, GEMM_SMEM);
    cudaFuncSetAttribute(tc_gemm_kernel<C_, 0>,
                         cudaFuncAttributeMaxDynamicSharedMemorySize, GEMM_SMEM);

    rope_tables_kernel<<<(T_ * 32 + 255) / 256, 256>>>();
    convert_split_kernel<<<(M_ * C_ / 4 + 255) / 256, 256>>>(x);
    convert_wT_kernel<0><<<dim3(N1_ / 32, C_ / 32), dim3(32, 8)>>>(W_attn);
    convert_wT_kernel<1><<<dim3(C_ / 32, C_ / 32), dim3(32, 8)>>>(W_proj);

    tc_gemm_kernel<N1_, 1><<<dim3(N1_ / 128, M_ / 128), 256, GEMM_SMEM>>>(b_attn, nullptr);

    attn_mma_kernel<<<dim3(T_ / 128, BHD), 256, ATTN_SMEM>>>();

    tc_gemm_kernel<C_, 0><<<dim3(C_ / 128, M_ / 128), 256, GEMM_SMEM>>>(b_proj, out);
}

// round 10
// speedup vs baseline: 2.2832x; 1.7203x over previous
#include <cuda_runtime.h>
#include <cuda_bf16.h>
#include <cuda_fp16.h>
#include <math.h>
#include <cstdint>

// Fixed problem shapes
#define B_   4
#define T_   2048
#define C_   768
#define H_   12
#define D_   64
#define M_   (B_ * T_)    // 8192
#define N1_  (3 * C_)     // 2304
#define BHD  (B_ * H_)    // 48

// ---------------- scratch (device globals; referenced ONLY in device code) --------
__device__ float g_cosT[T_ * (D_ / 2)];
__device__ float g_sinT[T_ * (D_ / 2)];

// fp16 operand buffers (single-pass everywhere; fp32 accumulate)
__device__ __half g_xf[M_ * C_];         // x
__device__ __half g_yf[M_ * C_];         // attn out
__device__ __half g_waf[N1_ * C_];       // W_attn^T [N][K]
__device__ __half g_wpf[C_ * C_];        // W_proj^T [N][K]
__device__ __half g_qh[BHD * T_ * D_];   // roped q (scaled 1/8), [B,H,T,D]
__device__ __half g_kh[BHD * T_ * D_];   // roped k
__device__ __half g_vth[BHD * D_ * T_];  // V^T [B,H,D,T]

// ---------------- helpers -----------------------------------------------------------
__device__ __forceinline__ uint32_t smem_u32(const void* p) {
    uint32_t a;
    asm("{ .reg .u64 t; cvta.to.shared.u64 t, %1; cvt.u32.u64 %0, t; }" : "=r"(a) : "l"(p));
    return a;
}
#define LDSM_X4(r, a)                                                           \
    asm volatile("ldmatrix.sync.aligned.m8n8.x4.shared.b16 {%0,%1,%2,%3},[%4];" \
        : "=r"((r)[0]), "=r"((r)[1]), "=r"((r)[2]), "=r"((r)[3]) : "r"(a))
#define MMAF16(d, a, b0, b1)                                                    \
    asm volatile("mma.sync.aligned.m16n8k16.row.col.f32.f16.f16.f32 "           \
        "{%0,%1,%2,%3},{%4,%5,%6,%7},{%8,%9},{%0,%1,%2,%3};"                    \
        : "+f"((d)[0]), "+f"((d)[1]), "+f"((d)[2]), "+f"((d)[3])                \
        : "r"((a)[0]), "r"((a)[1]), "r"((a)[2]), "r"((a)[3]), "r"(b0), "r"(b1))
#define CP16(dst, src) \
    asm volatile("cp.async.cg.shared.global [%0], [%1], 16;" :: "r"(dst), "l"(src))

__device__ __forceinline__ uint32_t h2(float a, float b) {
    __half2 t = __floats2half2_rn(a, b);
    return *(uint32_t*)&t;
}

// ---------------- RoPE tables ------------------------------------------------------
__global__ void rope_tables_kernel() {
    int idx = blockIdx.x * blockDim.x + threadIdx.x;
    if (idx >= T_ * 32) return;
    int t = idx >> 5;
    int i = idx & 31;
    double inv = exp(-((double)i / 32.0) * log(10000.0));
    double ang = (double)t * inv;
    g_cosT[idx] = (float)cos(ang);
    g_sinT[idx] = (float)sin(ang);
}

// ---------------- fp32 -> fp16 convert of x -----------------------------------------
__global__ void convert_x_kernel(const float* __restrict__ src) {
    const int n4 = M_ * C_ / 4;
    int i = blockIdx.x * blockDim.x + threadIdx.x;
    if (i >= n4) return;
    float4 v = ((const float4*)src)[i];
    ((uint2*)g_xf)[i] = make_uint2(h2(v.x, v.y), h2(v.z, v.w));
}

// ---------------- W[K][N] -> W^T[N][K] fp16 ------------------------------------------
template <int WHICH>
__global__ void convert_wT_kernel(const float* __restrict__ W) {
    const int K = C_;
    const int N = (WHICH == 0) ? N1_ : C_;
    __half* Th = (WHICH == 0) ? g_waf : g_wpf;
    __shared__ float tile[32][33];
    int k0 = blockIdx.y * 32, n0 = blockIdx.x * 32;
    int tx = threadIdx.x, ty = threadIdx.y;
    for (int r = ty; r < 32; r += 8)
        tile[r][tx] = W[(size_t)(k0 + r) * N + n0 + tx];
    __syncthreads();
    for (int r = ty; r < 32; r += 8)
        Th[(size_t)(n0 + r) * K + k0 + tx] = __float2half(tile[tx][r]);
}

// ---------------- mma.sync GEMM: fp16 single-pass, fp32 accum -----------------------
// D[128m,128n] = A[m,K].B^T[n,K] + bias. BK=32 double-buffered cp.async.
// 8 warps (4m x 2n), 32x64 per warp.
// EPI==1 (QKV): fused epilogue — RoPE q/k (q scaled 1/8) -> fp16 g_qh/g_kh,
//               V transposed -> fp16 g_vth.
// EPI==0 (proj): fp32 out + bias.
#define TILE_B    10240                 // 128 rows x 80B (64B data + 16 pad)
#define STAGE_B   (2 * TILE_B)          // A + B tiles
#define GEMM_SMEM 67584                 // epilogue stage 128x132 fp32 dominates

template <int NT, int EPI>
__global__ __launch_bounds__(256, 2) void tc_gemm_kernel(
    const float* __restrict__ bias, float* __restrict__ Cout)
{
    extern __shared__ __align__(128) char smem[];
    const uint32_t sb0 = smem_u32(smem);
    const int tid  = threadIdx.x;
    const int lane = tid & 31;
    const int warp = tid >> 5;
    const int m_w  = (warp >> 1) * 32;
    const int n_w  = (warp & 1) * 64;
    const int m0 = blockIdx.y * 128;
    const int n0 = blockIdx.x * 128;

    const __half* Asrc = (EPI == 1) ? g_xf  : g_yf;
    const __half* Bsrc = (EPI == 1) ? g_waf : g_wpf;

    auto load_chunk = [&](int kc, int st) {
        const uint32_t sbase = sb0 + (uint32_t)st * STAGE_B;
        const int k0 = kc * 32;
#pragma unroll
        for (int it = 0; it < 4; ++it) {
            int idx  = it * 256 + tid;
            int tile = idx >> 9;               // 0:A 1:B
            int r    = (idx >> 2) & 127;
            int seg  = idx & 3;
            const __half* src = tile ? Bsrc : Asrc;
            int rowbase = (tile ? n0 : m0) + r;
            const void* g = src + (size_t)rowbase * C_ + k0 + seg * 8;
            uint32_t dst = sbase + (uint32_t)tile * TILE_B + (uint32_t)(r * 80 + seg * 16);
            CP16(dst, g);
        }
        asm volatile("cp.async.commit_group;" ::: "memory");
    };

    float acc[2][8][4];
#pragma unroll
    for (int i = 0; i < 2; i++)
#pragma unroll
        for (int j = 0; j < 8; j++)
#pragma unroll
            for (int r = 0; r < 4; r++) acc[i][j][r] = 0.f;

    load_chunk(0, 0);
    const int NCHUNK = C_ / 32;   // 24
    for (int c = 0; c < NCHUNK; ++c) {
        const int st = c & 1;
        if (c + 1 < NCHUNK) {
            load_chunk(c + 1, st ^ 1);
            asm volatile("cp.async.wait_group 1;" ::: "memory");
        } else {
            asm volatile("cp.async.wait_group 0;" ::: "memory");
        }
        __syncthreads();

        const uint32_t sA = sb0 + (uint32_t)st * STAGE_B;
        const uint32_t sB = sA + TILE_B;

        uint32_t af[2][2][4];   // [ks][m-atom]
#pragma unroll
        for (int ks = 0; ks < 2; ks++)
#pragma unroll
            for (int i = 0; i < 2; i++) {
                uint32_t ra = (uint32_t)((m_w + i * 16 + (lane & 15)) * 80 +
                                         ks * 32 + ((lane >> 4) & 1) * 16);
                LDSM_X4(af[ks][i], sA + ra);
            }
#pragma unroll
        for (int j = 0; j < 8; j++) {
            uint32_t rb = (uint32_t)((n_w + j * 8 + (lane & 7)) * 80 +
                                     ((lane >> 3) & 3) * 16);
            uint32_t bF[4];
            LDSM_X4(bF, sB + rb);
#pragma unroll
            for (int ks = 0; ks < 2; ks++)
#pragma unroll
                for (int i = 0; i < 2; i++)
                    MMAF16(acc[i][j], af[ks][i], bF[ks * 2], bF[ks * 2 + 1]);
        }
        __syncthreads();
    }

    // ---- stage results (bias added) into smem ----
    float* stg = (float*)smem;   // 128 x 132
#pragma unroll
    for (int i = 0; i < 2; i++) {
        int row = m_w + i * 16 + (lane >> 2);
#pragma unroll
        for (int j = 0; j < 8; j++) {
            int col = n_w + j * 8 + (lane & 3) * 2;
            float b0 = bias[n0 + col], b1 = bias[n0 + col + 1];
            stg[row * 132 + col]           = acc[i][j][0] + b0;
            stg[row * 132 + col + 1]       = acc[i][j][1] + b1;
            stg[(row + 8) * 132 + col]     = acc[i][j][2] + b0;
            stg[(row + 8) * 132 + col + 1] = acc[i][j][3] + b1;
        }
    }
    __syncthreads();

    if (EPI == 0) {
#pragma unroll
        for (int it = 0; it < 16; ++it) {
            int idx = it * 256 + tid;
            int ml = idx >> 5;
            int c4 = (idx & 31) * 4;
            float4 v = *(const float4*)(stg + ml * 132 + c4);
            *(float4*)(Cout + (size_t)(m0 + ml) * NT + n0 + c4) = v;
        }
    } else {
        const int which = n0 / C_;               // 0=q 1=k 2=v
        const int hbase = (n0 % C_) / 64;
        const int bb = m0 >> 11;
        const int t0 = m0 & (T_ - 1);
        if (which < 2) {
            __half* dh = which ? g_kh : g_qh;
            const float sc = which ? 1.0f : 0.125f;
#pragma unroll
            for (int it = 0; it < 16; ++it) {
                int idx = it * 256 + tid;
                int ml = idx >> 5;
                int hl = (idx >> 4) & 1;
                int d  = (idx & 15) * 2;
                int t  = t0 + ml;
                float c0 = g_cosT[(t << 5) + d],     s0 = g_sinT[(t << 5) + d];
                float c1 = g_cosT[(t << 5) + d + 1], s1 = g_sinT[(t << 5) + d + 1];
                const float* row = stg + ml * 132 + hl * 64 + d;
                float x1a = row[0],  x1b = row[1];
                float x2a = row[32], x2b = row[33];
                float y1a = (x1a * c0 + x2a * s0) * sc;
                float y1b = (x1b * c1 + x2b * s1) * sc;
                float y2a = (-x1a * s0 + x2a * c0) * sc;
                float y2b = (-x1b * s1 + x2b * c1) * sc;
                size_t o = ((size_t)(bb * H_ + hbase + hl) * T_ + t) * 64 + d;
                *(uint32_t*)(dh + o)      = h2(y1a, y1b);
                *(uint32_t*)(dh + o + 32) = h2(y2a, y2b);
            }
        } else {
            // V: transpose into g_vth [bh][d][t] (fp16)
#pragma unroll
            for (int it = 0; it < 32; ++it) {
                int idx  = it * 256 + tid;
                int dcol = idx >> 6;
                int tp   = (idx & 63) * 2;
                int hl = dcol >> 6;
                int dd = dcol & 63;
                float v0 = stg[tp * 132 + dcol];
                float v1 = stg[(tp + 1) * 132 + dcol];
                size_t o = ((size_t)(bb * H_ + hbase + hl) * 64 + dd) * T_ + t0 + tp;
                *(uint32_t*)(g_vth + o) = h2(v0, v1);
            }
        }
    }
}

// ---------------- Tensor-core flash attention: fp16 single-pass --------------------
// CTA = 128 q rows; 8 warps x 16q x full 128-k tile. QK^T and PV single-pass fp16
// (fp32 accum). Stage = K (128x144B) + V^T (64x272B) = 35840B, double buffered.
#define KSTG  (128 * 144)                // 18432
#define VSTG  (64 * 272)                 // 17408
#define STG_BYTES (KSTG + VSTG)          // 35840
#define ATTN_SMEM (2 * STG_BYTES)        // 71680

__global__ __launch_bounds__(256, 1) void attn_mma_kernel() {
    extern __shared__ __align__(128) char sm[];
    const uint32_t sb = smem_u32(sm);
    const int tid  = threadIdx.x;
    const int lane = tid & 31;
    const int w    = tid >> 5;
    const int bh   = blockIdx.y;
    const int qb   = (int)gridDim.x - 1 - (int)blockIdx.x;   // longest first
    const int b    = bh / H_;
    const int h    = bh - b * H_;
    const size_t hb = (size_t)bh * T_ * D_;
    const int qbase = qb * 128;
    const int r0 = lane >> 2;
    const int c2 = (lane & 3) * 2;
    const int row_a = qbase + w * 16 + r0;

    // Q A-fragments: fp16, direct 4B global loads (pairs are d-contiguous)
    uint32_t qf[4][4];
#pragma unroll
    for (int ks = 0; ks < 4; ks++) {
        int d = ks * 16 + c2;
        size_t o0 = hb + (size_t)row_a * 64 + d;
        size_t o1 = hb + (size_t)(row_a + 8) * 64 + d;
        qf[ks][0] = *(const uint32_t*)(g_qh + o0);
        qf[ks][1] = *(const uint32_t*)(g_qh + o1);
        qf[ks][2] = *(const uint32_t*)(g_qh + o0 + 8);
        qf[ks][3] = *(const uint32_t*)(g_qh + o1 + 8);
    }

    const __half* kh = g_kh + hb;
    const __half* vh = g_vth + hb;

    auto load_stage = [&](int kt, int st) {
        const uint32_t sbase = sb + (uint32_t)st * STG_BYTES;
        const int kbase = kt * 128;
#pragma unroll
        for (int it = 0; it < 4; ++it) {            // K: 128 rows x 8 segs
            int idx = it * 256 + tid;
            int r   = idx >> 3;
            int seg = idx & 7;
            const void* g = kh + (size_t)(kbase + r) * 64 + seg * 8;
            CP16(sbase + (uint32_t)(r * 144 + seg * 16), g);
        }
#pragma unroll
        for (int it = 0; it < 4; ++it) {            // V^T: 64 d-rows x 16 segs
            int idx = it * 256 + tid;
            int r   = idx >> 4;
            int seg = idx & 15;
            const void* g = vh + (size_t)r * T_ + kbase + seg * 8;
            CP16(sbase + (uint32_t)(KSTG + r * 272 + seg * 16), g);
        }
        asm volatile("cp.async.commit_group;" ::: "memory");
    };

    float oacc[8][4];
#pragma unroll
    for (int jd = 0; jd < 8; jd++)
#pragma unroll
        for (int e = 0; e < 4; e++) oacc[jd][e] = 0.f;
    float m0 = -1e30f, m1 = -1e30f, l0 = 0.f, l1 = 0.f;

    load_stage(0, 0);

    for (int kt = 0; kt <= qb; kt++) {
        const int st = kt & 1;
        if (kt < qb) {
            load_stage(kt + 1, st ^ 1);
            asm volatile("cp.async.wait_group 1;" ::: "memory");
        } else {
            asm volatile("cp.async.wait_group 0;" ::: "memory");
        }
        __syncthreads();

        const uint32_t kb = sb + (uint32_t)st * STG_BYTES;

        // ---- S = Q K^T (single-pass fp16), 16 n8 acc tiles ----
        float sacc[16][4];
#pragma unroll
        for (int j = 0; j < 16; j++)
#pragma unroll
            for (int e = 0; e < 4; e++) sacc[j][e] = 0.f;

#pragma unroll
        for (int j = 0; j < 16; j++) {
            uint32_t rbase = kb + (uint32_t)((j * 8 + (lane & 7)) * 144 +
                                             ((lane >> 3) & 3) * 16);
#pragma unroll
            for (int half = 0; half < 2; half++) {
                uint32_t bF[4];
                LDSM_X4(bF, rbase + half * 64);
#pragma unroll
                for (int ki = 0; ki < 2; ki++) {
                    int ks = half * 2 + ki;
                    MMAF16(sacc[j], qf[ks], bF[ki * 2], bF[ki * 2 + 1]);
                }
            }
        }

        // ---- causal mask on diagonal tile ----
        if (kt == qb) {
            const int kbase = kt * 128;
#pragma unroll
            for (int j = 0; j < 16; j++) {
                int col = kbase + j * 8 + c2;
                if (col > row_a)         sacc[j][0] = -1e30f;
                if (col + 1 > row_a)     sacc[j][1] = -1e30f;
                if (col > row_a + 8)     sacc[j][2] = -1e30f;
                if (col + 1 > row_a + 8) sacc[j][3] = -1e30f;
            }
        }

        // ---- online softmax ----
        float mx0 = -1e30f, mx1 = -1e30f;
#pragma unroll
        for (int j = 0; j < 16; j++) {
            mx0 = fmaxf(mx0, fmaxf(sacc[j][0], sacc[j][1]));
            mx1 = fmaxf(mx1, fmaxf(sacc[j][2], sacc[j][3]));
        }
        mx0 = fmaxf(mx0, __shfl_xor_sync(0xffffffffu, mx0, 1));
        mx0 = fmaxf(mx0, __shfl_xor_sync(0xffffffffu, mx0, 2));
        mx1 = fmaxf(mx1, __shfl_xor_sync(0xffffffffu, mx1, 1));
        mx1 = fmaxf(mx1, __shfl_xor_sync(0xffffffffu, mx1, 2));
        float mn0 = fmaxf(m0, mx0), mn1 = fmaxf(m1, mx1);
        float a0 = __expf(m0 - mn0), a1 = __expf(m1 - mn1);
        m0 = mn0; m1 = mn1;
        float s0 = 0.f, s1 = 0.f;
#pragma unroll
        for (int j = 0; j < 16; j++) {
            sacc[j][0] = __expf(sacc[j][0] - m0);
            sacc[j][1] = __expf(sacc[j][1] - m0);
            sacc[j][2] = __expf(sacc[j][2] - m1);
            sacc[j][3] = __expf(sacc[j][3] - m1);
            s0 += sacc[j][0] + sacc[j][1];
            s1 += sacc[j][2] + sacc[j][3];
        }
        l0 = l0 * a0 + s0;
        l1 = l1 * a1 + s1;
#pragma unroll
        for (int jd = 0; jd < 8; jd++) {
            oacc[jd][0] *= a0; oacc[jd][1] *= a0;
            oacc[jd][2] *= a1; oacc[jd][3] *= a1;
        }

        // ---- PV: O += P V (P fp16 from acc frags, V^T fp16, single pass) ----
        const uint32_t vb = kb + KSTG;
#pragma unroll
        for (int koff = 0; koff < 4; koff++) {
            uint32_t pa[2][4];
#pragma unroll
            for (int ki = 0; ki < 2; ki++) {
                int j0 = (koff * 2 + ki) * 2;
                pa[ki][0] = h2(sacc[j0][0],     sacc[j0][1]);
                pa[ki][1] = h2(sacc[j0][2],     sacc[j0][3]);
                pa[ki][2] = h2(sacc[j0 + 1][0], sacc[j0 + 1][1]);
                pa[ki][3] = h2(sacc[j0 + 1][2], sacc[j0 + 1][3]);
            }
#pragma unroll
            for (int jd = 0; jd < 8; jd++) {
                uint32_t rv = vb + (uint32_t)((jd * 8 + (lane & 7)) * 272 +
                                              ((lane >> 3) & 3) * 16 + koff * 64);
                uint32_t vF[4];
                LDSM_X4(vF, rv);
#pragma unroll
                for (int ki = 0; ki < 2; ki++)
                    MMAF16(oacc[jd], pa[ki], vF[ki * 2], vF[ki * 2 + 1]);
            }
        }
        __syncthreads();
    }

    // ---- epilogue: normalize, fp16 store (proj GEMM input) ----
    l0 += __shfl_xor_sync(0xffffffffu, l0, 1);
    l0 += __shfl_xor_sync(0xffffffffu, l0, 2);
    l1 += __shfl_xor_sync(0xffffffffu, l1, 1);
    l1 += __shfl_xor_sync(0xffffffffu, l1, 2);
    const float inv0 = 1.f / l0, inv1 = 1.f / l1;
    const size_t y0 = ((size_t)(b * T_) + row_a) * C_ + h * 64;
    const size_t y1 = ((size_t)(b * T_) + row_a + 8) * C_ + h * 64;
#pragma unroll
    for (int jd = 0; jd < 8; jd++) {
        int d = jd * 8 + c2;
        *(uint32_t*)(g_yf + y0 + d) = h2(oacc[jd][0] * inv0, oacc[jd][1] * inv0);
        *(uint32_t*)(g_yf + y1 + d) = h2(oacc[jd][2] * inv1, oacc[jd][3] * inv1);
    }
}

// ---------------- launch ------------------------------------------------------------
extern "C" void kernel_launch(void* const* d_in, const int* in_sizes, int n_in,
                              void* d_out, int out_size) {
    (void)in_sizes; (void)n_in; (void)out_size;
    const float* x      = (const float*)d_in[0];
    const float* W_attn = (const float*)d_in[1];
    const float* b_attn = (const float*)d_in[2];
    const float* W_proj = (const float*)d_in[3];
    const float* b_proj = (const float*)d_in[4];
    float* out = (float*)d_out;

    cudaFuncSetAttribute(attn_mma_kernel, cudaFuncAttributeMaxDynamicSharedMemorySize,
                         ATTN_SMEM);
    cudaFuncSetAttribute(tc_gemm_kernel<N1_, 1>,
                         cudaFuncAttributeMaxDynamicSharedMemorySize, GEMM_SMEM);
    cudaFuncSetAttribute(tc_gemm_kernel<C_, 0>,
                         cudaFuncAttributeMaxDynamicSharedMemorySize, GEMM_SMEM);

    rope_tables_kernel<<<(T_ * 32 + 255) / 256, 256>>>();
    convert_x_kernel<<<(M_ * C_ / 4 + 255) / 256, 256>>>(x);
    convert_wT_kernel<0><<<dim3(N1_ / 32, C_ / 32), dim3(32, 8)>>>(W_attn);
    convert_wT_kernel<1><<<dim3(C_ / 32, C_ / 32), dim3(32, 8)>>>(W_proj);

    tc_gemm_kernel<N1_, 1><<<dim3(N1_ / 128, M_ / 128), 256, GEMM_SMEM>>>(b_attn, nullptr);

    attn_mma_kernel<<<dim3(T_ / 128, BHD), 256, ATTN_SMEM>>>();

    tc_gemm_kernel<C_, 0><<<dim3(C_ / 128, M_ / 128), 256, GEMM_SMEM>>>(b_proj, out);
}

// round 11
// speedup vs baseline: 2.4659x; 1.0800x over previous
#include <cuda_runtime.h>
#include <cuda_bf16.h>
#include <cuda_fp16.h>
#include <math.h>
#include <cstdint>

// Fixed problem shapes
#define B_   4
#define T_   2048
#define C_   768
#define H_   12
#define D_   64
#define M_   (B_ * T_)    // 8192
#define N1_  (3 * C_)     // 2304
#define BHD  (B_ * H_)    // 48

// ---------------- scratch (device globals; referenced ONLY in device code) --------
__device__ float g_cosT[T_ * (D_ / 2)];
__device__ float g_sinT[T_ * (D_ / 2)];

// fp16 operand buffers (single-pass everywhere; fp32 accumulate)
__device__ __half g_xf[M_ * C_];         // x
__device__ __half g_yf[M_ * C_];         // attn out
__device__ __half g_waf[N1_ * C_];       // W_attn^T [N][K]
__device__ __half g_wpf[C_ * C_];        // W_proj^T [N][K]
__device__ __half g_qh[BHD * T_ * D_];   // roped q (scaled 1/8), [B,H,T,D]
__device__ __half g_kh[BHD * T_ * D_];   // roped k
__device__ __half g_vth[BHD * D_ * T_];  // V^T [B,H,D,T]

// ---------------- helpers -----------------------------------------------------------
__device__ __forceinline__ uint32_t smem_u32(const void* p) {
    uint32_t a;
    asm("{ .reg .u64 t; cvta.to.shared.u64 t, %1; cvt.u32.u64 %0, t; }" : "=r"(a) : "l"(p));
    return a;
}
#define LDSM_X4(r, a)                                                           \
    asm volatile("ldmatrix.sync.aligned.m8n8.x4.shared.b16 {%0,%1,%2,%3},[%4];" \
        : "=r"((r)[0]), "=r"((r)[1]), "=r"((r)[2]), "=r"((r)[3]) : "r"(a))
#define MMAF16(d, a, b0, b1)                                                    \
    asm volatile("mma.sync.aligned.m16n8k16.row.col.f32.f16.f16.f32 "           \
        "{%0,%1,%2,%3},{%4,%5,%6,%7},{%8,%9},{%0,%1,%2,%3};"                    \
        : "+f"((d)[0]), "+f"((d)[1]), "+f"((d)[2]), "+f"((d)[3])                \
        : "r"((a)[0]), "r"((a)[1]), "r"((a)[2]), "r"((a)[3]), "r"(b0), "r"(b1))
#define CP16(dst, src) \
    asm volatile("cp.async.cg.shared.global [%0], [%1], 16;" :: "r"(dst), "l"(src))

__device__ __forceinline__ uint32_t h2(float a, float b) {
    __half2 t = __floats2half2_rn(a, b);
    return *(uint32_t*)&t;
}

// ---------------- RoPE tables ------------------------------------------------------
__global__ void rope_tables_kernel() {
    int idx = blockIdx.x * blockDim.x + threadIdx.x;
    if (idx >= T_ * 32) return;
    int t = idx >> 5;
    int i = idx & 31;
    double inv = exp(-((double)i / 32.0) * log(10000.0));
    double ang = (double)t * inv;
    g_cosT[idx] = (float)cos(ang);
    g_sinT[idx] = (float)sin(ang);
}

// ---------------- fp32 -> fp16 convert of x -----------------------------------------
__global__ void convert_x_kernel(const float* __restrict__ src) {
    const int n4 = M_ * C_ / 4;
    int i = blockIdx.x * blockDim.x + threadIdx.x;
    if (i >= n4) return;
    float4 v = ((const float4*)src)[i];
    ((uint2*)g_xf)[i] = make_uint2(h2(v.x, v.y), h2(v.z, v.w));
}

// ---------------- W[K][N] -> W^T[N][K] fp16 ------------------------------------------
template <int WHICH>
__global__ void convert_wT_kernel(const float* __restrict__ W) {
    const int K = C_;
    const int N = (WHICH == 0) ? N1_ : C_;
    __half* Th = (WHICH == 0) ? g_waf : g_wpf;
    __shared__ float tile[32][33];
    int k0 = blockIdx.y * 32, n0 = blockIdx.x * 32;
    int tx = threadIdx.x, ty = threadIdx.y;
    for (int r = ty; r < 32; r += 8)
        tile[r][tx] = W[(size_t)(k0 + r) * N + n0 + tx];
    __syncthreads();
    for (int r = ty; r < 32; r += 8)
        Th[(size_t)(n0 + r) * K + k0 + tx] = __float2half(tile[tx][r]);
}

// ---------------- mma.sync GEMM: fp16 single-pass, fp32 accum (unchanged) -----------
#define TILE_B    10240
#define STAGE_B   (2 * TILE_B)
#define GEMM_SMEM 67584

template <int NT, int EPI>
__global__ __launch_bounds__(256, 2) void tc_gemm_kernel(
    const float* __restrict__ bias, float* __restrict__ Cout)
{
    extern __shared__ __align__(128) char smem[];
    const uint32_t sb0 = smem_u32(smem);
    const int tid  = threadIdx.x;
    const int lane = tid & 31;
    const int warp = tid >> 5;
    const int m_w  = (warp >> 1) * 32;
    const int n_w  = (warp & 1) * 64;
    const int m0 = blockIdx.y * 128;
    const int n0 = blockIdx.x * 128;

    const __half* Asrc = (EPI == 1) ? g_xf  : g_yf;
    const __half* Bsrc = (EPI == 1) ? g_waf : g_wpf;

    auto load_chunk = [&](int kc, int st) {
        const uint32_t sbase = sb0 + (uint32_t)st * STAGE_B;
        const int k0 = kc * 32;
#pragma unroll
        for (int it = 0; it < 4; ++it) {
            int idx  = it * 256 + tid;
            int tile = idx >> 9;
            int r    = (idx >> 2) & 127;
            int seg  = idx & 3;
            const __half* src = tile ? Bsrc : Asrc;
            int rowbase = (tile ? n0 : m0) + r;
            const void* g = src + (size_t)rowbase * C_ + k0 + seg * 8;
            uint32_t dst = sbase + (uint32_t)tile * TILE_B + (uint32_t)(r * 80 + seg * 16);
            CP16(dst, g);
        }
        asm volatile("cp.async.commit_group;" ::: "memory");
    };

    float acc[2][8][4];
#pragma unroll
    for (int i = 0; i < 2; i++)
#pragma unroll
        for (int j = 0; j < 8; j++)
#pragma unroll
            for (int r = 0; r < 4; r++) acc[i][j][r] = 0.f;

    load_chunk(0, 0);
    const int NCHUNK = C_ / 32;
    for (int c = 0; c < NCHUNK; ++c) {
        const int st = c & 1;
        if (c + 1 < NCHUNK) {
            load_chunk(c + 1, st ^ 1);
            asm volatile("cp.async.wait_group 1;" ::: "memory");
        } else {
            asm volatile("cp.async.wait_group 0;" ::: "memory");
        }
        __syncthreads();

        const uint32_t sA = sb0 + (uint32_t)st * STAGE_B;
        const uint32_t sB = sA + TILE_B;

        uint32_t af[2][2][4];
#pragma unroll
        for (int ks = 0; ks < 2; ks++)
#pragma unroll
            for (int i = 0; i < 2; i++) {
                uint32_t ra = (uint32_t)((m_w + i * 16 + (lane & 15)) * 80 +
                                         ks * 32 + ((lane >> 4) & 1) * 16);
                LDSM_X4(af[ks][i], sA + ra);
            }
#pragma unroll
        for (int j = 0; j < 8; j++) {
            uint32_t rb = (uint32_t)((n_w + j * 8 + (lane & 7)) * 80 +
                                     ((lane >> 3) & 3) * 16);
            uint32_t bF[4];
            LDSM_X4(bF, sB + rb);
#pragma unroll
            for (int ks = 0; ks < 2; ks++)
#pragma unroll
                for (int i = 0; i < 2; i++)
                    MMAF16(acc[i][j], af[ks][i], bF[ks * 2], bF[ks * 2 + 1]);
        }
        __syncthreads();
    }

    float* stg = (float*)smem;
#pragma unroll
    for (int i = 0; i < 2; i++) {
        int row = m_w + i * 16 + (lane >> 2);
#pragma unroll
        for (int j = 0; j < 8; j++) {
            int col = n_w + j * 8 + (lane & 3) * 2;
            float b0 = bias[n0 + col], b1 = bias[n0 + col + 1];
            stg[row * 132 + col]           = acc[i][j][0] + b0;
            stg[row * 132 + col + 1]       = acc[i][j][1] + b1;
            stg[(row + 8) * 132 + col]     = acc[i][j][2] + b0;
            stg[(row + 8) * 132 + col + 1] = acc[i][j][3] + b1;
        }
    }
    __syncthreads();

    if (EPI == 0) {
#pragma unroll
        for (int it = 0; it < 16; ++it) {
            int idx = it * 256 + tid;
            int ml = idx >> 5;
            int c4 = (idx & 31) * 4;
            float4 v = *(const float4*)(stg + ml * 132 + c4);
            *(float4*)(Cout + (size_t)(m0 + ml) * NT + n0 + c4) = v;
        }
    } else {
        const int which = n0 / C_;
        const int hbase = (n0 % C_) / 64;
        const int bb = m0 >> 11;
        const int t0 = m0 & (T_ - 1);
        if (which < 2) {
            __half* dh = which ? g_kh : g_qh;
            const float sc = which ? 1.0f : 0.125f;
#pragma unroll
            for (int it = 0; it < 16; ++it) {
                int idx = it * 256 + tid;
                int ml = idx >> 5;
                int hl = (idx >> 4) & 1;
                int d  = (idx & 15) * 2;
                int t  = t0 + ml;
                float c0 = g_cosT[(t << 5) + d],     s0 = g_sinT[(t << 5) + d];
                float c1 = g_cosT[(t << 5) + d + 1], s1 = g_sinT[(t << 5) + d + 1];
                const float* row = stg + ml * 132 + hl * 64 + d;
                float x1a = row[0],  x1b = row[1];
                float x2a = row[32], x2b = row[33];
                float y1a = (x1a * c0 + x2a * s0) * sc;
                float y1b = (x1b * c1 + x2b * s1) * sc;
                float y2a = (-x1a * s0 + x2a * c0) * sc;
                float y2b = (-x1b * s1 + x2b * c1) * sc;
                size_t o = ((size_t)(bb * H_ + hbase + hl) * T_ + t) * 64 + d;
                *(uint32_t*)(dh + o)      = h2(y1a, y1b);
                *(uint32_t*)(dh + o + 32) = h2(y2a, y2b);
            }
        } else {
#pragma unroll
            for (int it = 0; it < 32; ++it) {
                int idx  = it * 256 + tid;
                int dcol = idx >> 6;
                int tp   = (idx & 63) * 2;
                int hl = dcol >> 6;
                int dd = dcol & 63;
                float v0 = stg[tp * 132 + dcol];
                float v1 = stg[(tp + 1) * 132 + dcol];
                size_t o = ((size_t)(bb * H_ + hbase + hl) * 64 + dd) * T_ + t0 + tp;
                *(uint32_t*)(g_vth + o) = h2(v0, v1);
            }
        }
    }
}

// ---------------- Tensor-core flash attention: fp16, 2 CTA/SM ----------------------
// 128-k load stages (unchanged cadence); softmax/PV processed in two 64-k halves
// so live register state fits 128 regs -> 2 CTAs/SM. Global LPT CTA ordering.
#define KSTG  (128 * 144)                // 18432
#define VSTG  (64 * 272)                 // 17408
#define STG_BYTES (KSTG + VSTG)          // 35840
#define ATTN_SMEM (2 * STG_BYTES)        // 71680

__global__ __launch_bounds__(256, 2) void attn_mma_kernel() {
    extern __shared__ __align__(128) char sm[];
    const uint32_t sb = smem_u32(sm);
    const int tid  = threadIdx.x;
    const int lane = tid & 31;
    const int w    = tid >> 5;
    // LPT: all qb=15 tiles (across heads) first, then qb=14, ...
    const int bh   = (int)blockIdx.x % BHD;
    const int qb   = (T_ / 128) - 1 - (int)blockIdx.x / BHD;
    const int b    = bh / H_;
    const int h    = bh - b * H_;
    const size_t hb = (size_t)bh * T_ * D_;
    const int qbase = qb * 128;
    const int r0 = lane >> 2;
    const int c2 = (lane & 3) * 2;
    const int row_a = qbase + w * 16 + r0;

    // Q A-fragments: fp16, direct 4B global loads
    uint32_t qf[4][4];
#pragma unroll
    for (int ks = 0; ks < 4; ks++) {
        int d = ks * 16 + c2;
        size_t o0 = hb + (size_t)row_a * 64 + d;
        size_t o1 = hb + (size_t)(row_a + 8) * 64 + d;
        qf[ks][0] = *(const uint32_t*)(g_qh + o0);
        qf[ks][1] = *(const uint32_t*)(g_qh + o1);
        qf[ks][2] = *(const uint32_t*)(g_qh + o0 + 8);
        qf[ks][3] = *(const uint32_t*)(g_qh + o1 + 8);
    }

    const __half* kh = g_kh + hb;
    const __half* vh = g_vth + hb;

    auto load_stage = [&](int kt, int st) {
        const uint32_t sbase = sb + (uint32_t)st * STG_BYTES;
        const int kbase = kt * 128;
#pragma unroll
        for (int it = 0; it < 4; ++it) {
            int idx = it * 256 + tid;
            int r   = idx >> 3;
            int seg = idx & 7;
            const void* g = kh + (size_t)(kbase + r) * 64 + seg * 8;
            CP16(sbase + (uint32_t)(r * 144 + seg * 16), g);
        }
#pragma unroll
        for (int it = 0; it < 4; ++it) {
            int idx = it * 256 + tid;
            int r   = idx >> 4;
            int seg = idx & 15;
            const void* g = vh + (size_t)r * T_ + kbase + seg * 8;
            CP16(sbase + (uint32_t)(KSTG + r * 272 + seg * 16), g);
        }
        asm volatile("cp.async.commit_group;" ::: "memory");
    };

    float oacc[8][4];
#pragma unroll
    for (int jd = 0; jd < 8; jd++)
#pragma unroll
        for (int e = 0; e < 4; e++) oacc[jd][e] = 0.f;
    float m0 = -1e30f, m1 = -1e30f, l0 = 0.f, l1 = 0.f;

    load_stage(0, 0);

    for (int kt = 0; kt <= qb; kt++) {
        const int st = kt & 1;
        if (kt < qb) {
            load_stage(kt + 1, st ^ 1);
            asm volatile("cp.async.wait_group 1;" ::: "memory");
        } else {
            asm volatile("cp.async.wait_group 0;" ::: "memory");
        }
        __syncthreads();

        const uint32_t kb = sb + (uint32_t)st * STG_BYTES;
        const uint32_t vb = kb + KSTG;

#pragma unroll
        for (int khalf = 0; khalf < 2; khalf++) {
            // On the diagonal tile, the upper k-half is fully masked for the
            // lower 4 warps (rows < qbase+64 <= all cols): exact zero mass.
            if (kt == qb && khalf == 1 && w < 4) continue;

            // ---- S = Q K^T over 64 k (8 n8 tiles) ----
            float sacc[8][4];
#pragma unroll
            for (int j = 0; j < 8; j++)
#pragma unroll
                for (int e = 0; e < 4; e++) sacc[j][e] = 0.f;

#pragma unroll
            for (int j = 0; j < 8; j++) {
                uint32_t rbase = kb + (uint32_t)((khalf * 64 + j * 8 + (lane & 7)) * 144 +
                                                 ((lane >> 3) & 3) * 16);
#pragma unroll
                for (int dh = 0; dh < 2; dh++) {
                    uint32_t bF[4];
                    LDSM_X4(bF, rbase + dh * 64);
#pragma unroll
                    for (int ki = 0; ki < 2; ki++)
                        MMAF16(sacc[j], qf[dh * 2 + ki], bF[ki * 2], bF[ki * 2 + 1]);
                }
            }

            // ---- causal mask on diagonal tile ----
            if (kt == qb) {
                const int kb0 = kt * 128 + khalf * 64;
#pragma unroll
                for (int j = 0; j < 8; j++) {
                    int col = kb0 + j * 8 + c2;
                    if (col > row_a)         sacc[j][0] = -1e30f;
                    if (col + 1 > row_a)     sacc[j][1] = -1e30f;
                    if (col > row_a + 8)     sacc[j][2] = -1e30f;
                    if (col + 1 > row_a + 8) sacc[j][3] = -1e30f;
                }
            }

            // ---- online softmax over this 64-k half ----
            float mx0 = -1e30f, mx1 = -1e30f;
#pragma unroll
            for (int j = 0; j < 8; j++) {
                mx0 = fmaxf(mx0, fmaxf(sacc[j][0], sacc[j][1]));
                mx1 = fmaxf(mx1, fmaxf(sacc[j][2], sacc[j][3]));
            }
            mx0 = fmaxf(mx0, __shfl_xor_sync(0xffffffffu, mx0, 1));
            mx0 = fmaxf(mx0, __shfl_xor_sync(0xffffffffu, mx0, 2));
            mx1 = fmaxf(mx1, __shfl_xor_sync(0xffffffffu, mx1, 1));
            mx1 = fmaxf(mx1, __shfl_xor_sync(0xffffffffu, mx1, 2));
            float mn0 = fmaxf(m0, mx0), mn1 = fmaxf(m1, mx1);
            float a0 = __expf(m0 - mn0), a1 = __expf(m1 - mn1);
            m0 = mn0; m1 = mn1;
            float s0 = 0.f, s1 = 0.f;
#pragma unroll
            for (int j = 0; j < 8; j++) {
                sacc[j][0] = __expf(sacc[j][0] - m0);
                sacc[j][1] = __expf(sacc[j][1] - m0);
                sacc[j][2] = __expf(sacc[j][2] - m1);
                sacc[j][3] = __expf(sacc[j][3] - m1);
                s0 += sacc[j][0] + sacc[j][1];
                s1 += sacc[j][2] + sacc[j][3];
            }
            l0 = l0 * a0 + s0;
            l1 = l1 * a1 + s1;
#pragma unroll
            for (int jd = 0; jd < 8; jd++) {
                oacc[jd][0] *= a0; oacc[jd][1] *= a0;
                oacc[jd][2] *= a1; oacc[jd][3] *= a1;
            }

            // ---- PV over this 64-k half ----
#pragma unroll
            for (int koff = 0; koff < 2; koff++) {
                uint32_t pa[2][4];
#pragma unroll
                for (int ki = 0; ki < 2; ki++) {
                    int j0 = (koff * 2 + ki) * 2;
                    pa[ki][0] = h2(sacc[j0][0],     sacc[j0][1]);
                    pa[ki][1] = h2(sacc[j0][2],     sacc[j0][3]);
                    pa[ki][2] = h2(sacc[j0 + 1][0], sacc[j0 + 1][1]);
                    pa[ki][3] = h2(sacc[j0 + 1][2], sacc[j0 + 1][3]);
                }
#pragma unroll
                for (int jd = 0; jd < 8; jd++) {
                    uint32_t rv = vb + (uint32_t)((jd * 8 + (lane & 7)) * 272 +
                                                  ((lane >> 3) & 3) * 16 +
                                                  (khalf * 2 + koff) * 64);
                    uint32_t vF[4];
                    LDSM_X4(vF, rv);
#pragma unroll
                    for (int ki = 0; ki < 2; ki++)
                        MMAF16(oacc[jd], pa[ki], vF[ki * 2], vF[ki * 2 + 1]);
                }
            }
        }
        __syncthreads();
    }

    // ---- epilogue: normalize, fp16 store (proj GEMM input) ----
    l0 += __shfl_xor_sync(0xffffffffu, l0, 1);
    l0 += __shfl_xor_sync(0xffffffffu, l0, 2);
    l1 += __shfl_xor_sync(0xffffffffu, l1, 1);
    l1 += __shfl_xor_sync(0xffffffffu, l1, 2);
    const float inv0 = 1.f / l0, inv1 = 1.f / l1;
    const size_t y0 = ((size_t)(b * T_) + row_a) * C_ + h * 64;
    const size_t y1 = ((size_t)(b * T_) + row_a + 8) * C_ + h * 64;
#pragma unroll
    for (int jd = 0; jd < 8; jd++) {
        int d = jd * 8 + c2;
        *(uint32_t*)(g_yf + y0 + d) = h2(oacc[jd][0] * inv0, oacc[jd][1] * inv0);
        *(uint32_t*)(g_yf + y1 + d) = h2(oacc[jd][2] * inv1, oacc[jd][3] * inv1);
    }
}

// ---------------- launch ------------------------------------------------------------
extern "C" void kernel_launch(void* const* d_in, const int* in_sizes, int n_in,
                              void* d_out, int out_size) {
    (void)in_sizes; (void)n_in; (void)out_size;
    const float* x      = (const float*)d_in[0];
    const float* W_attn = (const float*)d_in[1];
    const float* b_attn = (const float*)d_in[2];
    const float* W_proj = (const float*)d_in[3];
    const float* b_proj = (const float*)d_in[4];
    float* out = (float*)d_out;

    cudaFuncSetAttribute(attn_mma_kernel, cudaFuncAttributeMaxDynamicSharedMemorySize,
                         ATTN_SMEM);
    cudaFuncSetAttribute(tc_gemm_kernel<N1_, 1>,
                         cudaFuncAttributeMaxDynamicSharedMemorySize, GEMM_SMEM);
    cudaFuncSetAttribute(tc_gemm_kernel<C_, 0>,
                         cudaFuncAttributeMaxDynamicSharedMemorySize, GEMM_SMEM);

    rope_tables_kernel<<<(T_ * 32 + 255) / 256, 256>>>();
    convert_x_kernel<<<(M_ * C_ / 4 + 255) / 256, 256>>>(x);
    convert_wT_kernel<0><<<dim3(N1_ / 32, C_ / 32), dim3(32, 8)>>>(W_attn);
    convert_wT_kernel<1><<<dim3(C_ / 32, C_ / 32), dim3(32, 8)>>>(W_proj);

    tc_gemm_kernel<N1_, 1><<<dim3(N1_ / 128, M_ / 128), 256, GEMM_SMEM>>>(b_attn, nullptr);

    attn_mma_kernel<<<(T_ / 128) * BHD, 256, ATTN_SMEM>>>();

    tc_gemm_kernel<C_, 0><<<dim3(C_ / 128, M_ / 128), 256, GEMM_SMEM>>>(b_proj, out);
}